// round 13
// baseline (speedup 1.0000x reference)
#include <cuda_runtime.h>
#include <cuda_bf16.h>
#include <cuda_fp16.h>
#include <math.h>

// ---------------------------------------------------------------------------
// Problem constants
// ---------------------------------------------------------------------------
#define ND   20000
#define NF   50000
#define NT   (ND + NF)
#define EE   400000
#define NLYR 2
#define OUTC 32
#define NBF  98   // cdiv(NF,512)
#define NBD  40   // cdiv(ND,512)

// ---------------------------------------------------------------------------
// Scratch pool (static device memory; no allocations anywhere)
// Global row convention: rows 0..ND-1 = device nodes, ND..NT-1 = feature nodes.
// ---------------------------------------------------------------------------
constexpr size_t NT128 = (size_t)NT * 128;

constexpr size_t OFF_X    = 0;                       // fp32 [NT][128]
constexpr size_t OFF_Q    = OFF_X   + NT128;         // fp32 [NT][128]
constexpr size_t OFF_KTV  = OFF_Q   + NT128;         // half [NT][256]
constexpr size_t OFF_XH   = OFF_KTV + NT128;         // bf16 [NT][128]
constexpr size_t OFF_XL   = OFF_XH  + NT128 / 2;
constexpr size_t OFF_AGH  = OFF_XL  + NT128 / 2;     // bf16 [NT][128]
constexpr size_t OFF_AGL  = OFF_AGH + NT128 / 2;
constexpr size_t OFF_WKE  = OFF_AGL + NT128 / 2;     // 4*16384 fp32
constexpr size_t OFF_WVE  = OFF_WKE + 65536;
constexpr size_t OFF_BKE  = OFF_WVE + 65536;         // 512
constexpr size_t OFF_BVE  = OFF_BKE + 512;
constexpr size_t OFF_HQ   = OFF_BVE + 512;           // bf16 4*16384 = 32768 floats each
constexpr size_t OFF_LQ   = OFF_HQ  + 32768;
constexpr size_t OFF_HK   = OFF_LQ  + 32768;
constexpr size_t OFF_LK   = OFF_HK  + 32768;
constexpr size_t OFF_HV   = OFF_LK  + 32768;
constexpr size_t OFF_LV   = OFF_HV  + 32768;
constexpr size_t OFF_HA   = OFF_LV  + 32768;
constexpr size_t OFF_LA   = OFF_HA  + 32768;
constexpr size_t OFF_HDI  = OFF_LA  + 32768;         // 8192 floats each
constexpr size_t OFF_LDI  = OFF_HDI + 8192;
constexpr size_t OFF_HFI  = OFF_LDI + 8192;
constexpr size_t OFF_LFI  = OFF_HFI + 8192;
constexpr size_t OFF_RPF  = OFF_LFI + 8192;          // NF+1 int
constexpr size_t OFF_RPD  = OFF_RPF + (NF + 1);      // ND+1 int
constexpr size_t OFF_CDF  = OFF_RPD + (ND + 1);      // EE int
constexpr size_t OFF_CFD  = OFF_CDF + EE;            // EE int
constexpr size_t OFF_CNT  = OFF_CFD + EE;            // NT int (F first, then D)
constexpr size_t OFF_CUR  = OFF_CNT + NT;            // NT int
constexpr size_t OFF_BSUM = OFF_CUR + NT;            // 160
constexpr size_t POOL_SZ  = OFF_BSUM + 160;

__device__ __align__(256) float g_pool[POOL_SZ];

// ---------------------------------------------------------------------------
// Helpers
// ---------------------------------------------------------------------------
__device__ __forceinline__ float gelu_exact(float v) {
    return 0.5f * v * (1.0f + erff(v * 0.70710678118654752440f));
}
__device__ __forceinline__ unsigned pack_bf16x2(float a, float b) {
    unsigned r;
    asm("cvt.rn.bf16x2.f32 %0, %1, %2;" : "=r"(r) : "f"(b), "f"(a));
    return r;
}
__device__ __forceinline__ void split_pair(float2 p, unsigned& hi, unsigned& lo) {
    unsigned h = pack_bf16x2(p.x, p.y);
    unsigned hx, hy;
    asm("prmt.b32 %0, 0, %1, 0x5400;" : "=r"(hx) : "r"(h));
    asm("prmt.b32 %0, 0, %1, 0x7600;" : "=r"(hy) : "r"(h));
    float lx = p.x - __uint_as_float(hx);
    float ly = p.y - __uint_as_float(hy);
    lo = pack_bf16x2(lx, ly);
    hi = h;
}
__device__ __forceinline__ void store_split(float v0, float v1, float* X,
                                            __nv_bfloat16* Xh, __nv_bfloat16* Xl,
                                            size_t base) {
    *(float2*)(X + base) = make_float2(v0, v1);
    unsigned h, l;
    split_pair(make_float2(v0, v1), h, l);
    *(unsigned*)(Xh + base) = h;
    *(unsigned*)(Xl + base) = l;
}

#define MMA_BF16(d, a, b0v, b1v)                                              \
    asm volatile(                                                             \
        "mma.sync.aligned.m16n8k16.row.col.f32.bf16.bf16.f32 "                \
        "{%0,%1,%2,%3},{%4,%5,%6,%7},{%8,%9},{%0,%1,%2,%3};"                  \
        : "+f"((d)[0]), "+f"((d)[1]), "+f"((d)[2]), "+f"((d)[3])              \
        : "r"((a)[0]), "r"((a)[1]), "r"((a)[2]), "r"((a)[3]),                 \
          "r"(b0v), "r"(b1v))

__device__ __forceinline__ void cp16(unsigned dst, const void* src, bool pred) {
    if (pred)
        asm volatile("cp.async.cg.shared.global [%0], [%1], 16;"
                     :: "r"(dst), "l"(src));
}
__device__ __forceinline__ unsigned cvta(const void* p) {
    return (unsigned)__cvta_generic_to_shared(p);
}

// ---------------------------------------------------------------------------
// GEMM argument bundle
// ---------------------------------------------------------------------------
struct GArgs {
    const float* AfD; const float* AfF;               // APATH0 A (per side)
    const __nv_bfloat16* Ah; const __nv_bfloat16* Al; // APATH1 A (global rows)
    const __nv_bfloat16 *H0, *L0, *H1, *L1, *H2, *L2; // weight family bases
    const float *b0, *b1, *b2;                        // bias bases
    float* Q; __half* KTV;                            // MODE0 outputs
    float* X; __nv_bfloat16 *Xh, *Xl;                 // MODE1/2 outputs
    const float *skipv, *lng, *lnb;                   // MODE2
    int layer, blkD;
};

// ---------------------------------------------------------------------------
// Tensor-core GEMM, bf16-split, merged D/F sides (side = blockIdx.x >= blkD).
//   MODE 0 (APATH1): 2-TERM split (ahi*bh + ahi*bl; A truncated to bf16).
//                    y=0 -> fp32 Q; y=1 -> fp16 kt into KTV; y=2 -> fp16 vt
//   MODE 1 (APATH0): 3-term. relu(A@W+b) -> X fp32 + Xh/Xl bf16
//   MODE 2 (APATH1): 3-term. X = LN(X + sk*(A@W+b) + (1-sk)X) -> X + Xh/Xl
// 128x128 tile, BK=16, 8 warps, cp.async double buffer.
// ---------------------------------------------------------------------------
template <int MODE, int APATH>
__global__ void __launch_bounds__(256)
gemm_tc(GArgs a) {
    constexpr bool TWO_TERM = (MODE == 0);   // MODE0 drops the alo term

    const int bx = blockIdx.x;
    const bool isF = bx >= a.blkD;
    const int lbx = isF ? bx - a.blkD : bx;
    const int combo = a.layer * 2 + (isF ? 1 : 0);

    int aRow0, aN, cOff;
    const float* Af = nullptr;
    if (APATH == 0) {
        aRow0 = lbx * 128;
        aN    = isF ? NF : ND;
        cOff  = isF ? ND : 0;
        Af    = isF ? a.AfF : a.AfD;
    } else {
        aRow0 = isF ? (ND + lbx * 128) : lbx * 128;
        aN    = isF ? NT : ND;
        cOff  = 0;
    }

    const __nv_bfloat16* WH;
    const __nv_bfloat16* WL;
    const float* bias;
    if (MODE == 1) {
        WH = isF ? a.H1 : a.H0;  WL = isF ? a.L1 : a.L0;
        bias = isF ? a.b1 : a.b0;
    } else if (MODE == 0) {
        int fam = blockIdx.y;
        WH = (fam == 0 ? a.H0 : fam == 1 ? a.H1 : a.H2) + (size_t)combo * 16384;
        WL = (fam == 0 ? a.L0 : fam == 1 ? a.L1 : a.L2) + (size_t)combo * 16384;
        bias = (fam == 0 ? a.b0 : fam == 1 ? a.b1 : a.b2) + combo * 128;
    } else {
        WH = a.H0 + (size_t)combo * 16384;
        WL = a.L0 + (size_t)combo * 16384;
        bias = a.b0 + combo * 128;
    }

    constexpr int A_RAW = (APATH == 0) ? (2 * 128 * 20 * 4)
                        : (TWO_TERM ? (2 * 128 * 16 * 2) : (2 * (2 * 128 * 16 * 2)));
    __shared__ __align__(16) unsigned char AsRaw[A_RAW];
    __shared__ __align__(16) __nv_bfloat16 Bh[2][128 * 24];
    __shared__ __align__(16) __nv_bfloat16 Bl[2][128 * 24];
    __shared__ float rs[128], rq[128];

    float* Asf = (float*)AsRaw;                                  // [2][128*20]
    __nv_bfloat16* Ahs = (__nv_bfloat16*)AsRaw;                  // [2][128*16]
    __nv_bfloat16* Als = (__nv_bfloat16*)(AsRaw + (TWO_TERM ? 0 : 2 * 128 * 16 * 2));

    const int tid  = threadIdx.x;
    const int lane = tid & 31, warp = tid >> 5;
    const int g = lane >> 2, c = lane & 3;
    const int m0 = (warp >> 1) * 32, n0 = (warp & 1) * 64;

    auto stage = [&](int buf, int k0) {
        if (APATH == 0) {
#pragma unroll
            for (int i = 0; i < 2; i++) {
                int id = tid + i * 256;
                int r = id >> 2, ch = id & 3;
                cp16(cvta(&Asf[buf * 2560 + r * 20 + ch * 4]),
                     Af + (size_t)(aRow0 + r) * 128 + k0 + ch * 4, aRow0 + r < aN);
            }
        } else {
            int r = tid >> 1, ch = tid & 1;
            bool ok = aRow0 + r < aN;
            cp16(cvta(&Ahs[buf * 2048 + r * 16 + ch * 8]),
                 a.Ah + (size_t)(aRow0 + r) * 128 + k0 + ch * 8, ok);
            if (!TWO_TERM)
                cp16(cvta(&Als[buf * 2048 + r * 16 + ch * 8]),
                     a.Al + (size_t)(aRow0 + r) * 128 + k0 + ch * 8, ok);
        }
        int n = tid >> 1, ch = tid & 1;
        cp16(cvta(&Bh[buf][n * 24 + ch * 8]), WH + (size_t)n * 128 + k0 + ch * 8, true);
        cp16(cvta(&Bl[buf][n * 24 + ch * 8]), WL + (size_t)n * 128 + k0 + ch * 8, true);
        asm volatile("cp.async.commit_group;");
    };

    float acc[2][8][4];
#pragma unroll
    for (int mi = 0; mi < 2; mi++)
#pragma unroll
        for (int ni = 0; ni < 8; ni++)
#pragma unroll
            for (int j = 0; j < 4; j++) acc[mi][ni][j] = 0.f;

    stage(0, 0);

    for (int it = 0; it < 8; it++) {
        if (it < 7) {
            stage((it + 1) & 1, (it + 1) * 16);
            asm volatile("cp.async.wait_group 1;");
        } else {
            asm volatile("cp.async.wait_group 0;");
        }
        __syncthreads();

        unsigned ahi[2][4], alo[2][4];
        if (APATH == 0) {
            const float* Ab = &Asf[(it & 1) * 2560];
#pragma unroll
            for (int mi = 0; mi < 2; mi++) {
                int rb = (m0 + mi * 16 + g) * 20;
                split_pair(*(const float2*)&Ab[rb + 2 * c],           ahi[mi][0], alo[mi][0]);
                split_pair(*(const float2*)&Ab[rb + 160 + 2 * c],     ahi[mi][1], alo[mi][1]);
                split_pair(*(const float2*)&Ab[rb + 2 * c + 8],       ahi[mi][2], alo[mi][2]);
                split_pair(*(const float2*)&Ab[rb + 160 + 2 * c + 8], ahi[mi][3], alo[mi][3]);
            }
        } else {
            const __nv_bfloat16* Abh = &Ahs[(it & 1) * 2048];
#pragma unroll
            for (int mi = 0; mi < 2; mi++) {
                int rb = (m0 + mi * 16 + g) * 16;
                ahi[mi][0] = *(const unsigned*)&Abh[rb + 2 * c];
                ahi[mi][1] = *(const unsigned*)&Abh[rb + 128 + 2 * c];
                ahi[mi][2] = *(const unsigned*)&Abh[rb + 2 * c + 8];
                ahi[mi][3] = *(const unsigned*)&Abh[rb + 128 + 2 * c + 8];
            }
            if (!TWO_TERM) {
                const __nv_bfloat16* Abl = &Als[(it & 1) * 2048];
#pragma unroll
                for (int mi = 0; mi < 2; mi++) {
                    int rb = (m0 + mi * 16 + g) * 16;
                    alo[mi][0] = *(const unsigned*)&Abl[rb + 2 * c];
                    alo[mi][1] = *(const unsigned*)&Abl[rb + 128 + 2 * c];
                    alo[mi][2] = *(const unsigned*)&Abl[rb + 2 * c + 8];
                    alo[mi][3] = *(const unsigned*)&Abl[rb + 128 + 2 * c + 8];
                }
            }
        }
        const __nv_bfloat16* Bhh = Bh[it & 1];
        const __nv_bfloat16* Bll = Bl[it & 1];
#pragma unroll
        for (int ni = 0; ni < 8; ni++) {
            int bn = n0 + ni * 8 + g;
            unsigned bh0 = *(const unsigned*)&Bhh[bn * 24 + 2 * c];
            unsigned bh1 = *(const unsigned*)&Bhh[bn * 24 + 2 * c + 8];
            unsigned bl0 = *(const unsigned*)&Bll[bn * 24 + 2 * c];
            unsigned bl1 = *(const unsigned*)&Bll[bn * 24 + 2 * c + 8];
#pragma unroll
            for (int mi = 0; mi < 2; mi++) {
                MMA_BF16(acc[mi][ni], ahi[mi], bh0, bh1);
                MMA_BF16(acc[mi][ni], ahi[mi], bl0, bl1);
                if (!TWO_TERM) MMA_BF16(acc[mi][ni], alo[mi], bh0, bh1);
            }
        }
        __syncthreads();
    }

    if (MODE == 0 && blockIdx.y != 0) {
        // fp16 packed kt/vt epilogue
        const int voff = (blockIdx.y == 2) ? 4 : 0;
#pragma unroll
        for (int ni = 0; ni < 8; ni++) {
            int col = n0 + ni * 8 + 2 * c;
            float bb0 = bias[col], bb1 = bias[col + 1];
            int po = ((col >> 2) << 3) + (col & 3) + voff;
#pragma unroll
            for (int mi = 0; mi < 2; mi++) {
                int ra = aRow0 + m0 + mi * 16 + g;
                if (ra < aN)
                    *(__half2*)(a.KTV + (size_t)ra * 256 + po) =
                        __floats2half2_rn(acc[mi][ni][0] + bb0, acc[mi][ni][1] + bb1);
                if (ra + 8 < aN)
                    *(__half2*)(a.KTV + (size_t)(ra + 8) * 256 + po) =
                        __floats2half2_rn(acc[mi][ni][2] + bb0, acc[mi][ni][3] + bb1);
            }
        }
    } else if (MODE == 0) {
        // fp32 q epilogue
#pragma unroll
        for (int ni = 0; ni < 8; ni++) {
            int col = n0 + ni * 8 + 2 * c;
            float bb0 = bias[col], bb1 = bias[col + 1];
#pragma unroll
            for (int mi = 0; mi < 2; mi++) {
                int ra = aRow0 + m0 + mi * 16 + g;
                if (ra < aN)
                    *(float2*)(a.Q + (size_t)ra * 128 + col) =
                        make_float2(acc[mi][ni][0] + bb0, acc[mi][ni][1] + bb1);
                if (ra + 8 < aN)
                    *(float2*)(a.Q + (size_t)(ra + 8) * 128 + col) =
                        make_float2(acc[mi][ni][2] + bb0, acc[mi][ni][3] + bb1);
            }
        }
    } else if (MODE == 1) {
        // relu -> X + Xh/Xl
#pragma unroll
        for (int ni = 0; ni < 8; ni++) {
            int col = n0 + ni * 8 + 2 * c;
            float bb0 = bias[col], bb1 = bias[col + 1];
#pragma unroll
            for (int mi = 0; mi < 2; mi++) {
                int ra = aRow0 + m0 + mi * 16 + g;
                if (ra < aN) {
                    float v0 = fmaxf(acc[mi][ni][0] + bb0, 0.f);
                    float v1 = fmaxf(acc[mi][ni][1] + bb1, 0.f);
                    store_split(v0, v1, a.X, a.Xh, a.Xl, (size_t)(ra + cOff) * 128 + col);
                }
                if (ra + 8 < aN) {
                    float v2 = fmaxf(acc[mi][ni][2] + bb0, 0.f);
                    float v3 = fmaxf(acc[mi][ni][3] + bb1, 0.f);
                    store_split(v2, v3, a.X, a.Xh, a.Xl, (size_t)(ra + 8 + cOff) * 128 + col);
                }
            }
        }
    } else {
        // MODE 2: fused skip + residual + LayerNorm (in-place on X, global rows)
        float sk = 1.f / (1.f + __expf(-a.skipv[combo]));
        float tms = 2.f - sk;
        const float* lng = a.lng + combo * 128;
        const float* lnb = a.lnb + combo * 128;
        if (tid < 128) { rs[tid] = 0.f; rq[tid] = 0.f; }
        __syncthreads();

        float psum[2][2] = {{0.f, 0.f}, {0.f, 0.f}};
        float psq[2][2]  = {{0.f, 0.f}, {0.f, 0.f}};
#pragma unroll
        for (int ni = 0; ni < 8; ni++) {
            int col = n0 + ni * 8 + 2 * c;
            float bb0 = bias[col], bb1 = bias[col + 1];
#pragma unroll
            for (int mi = 0; mi < 2; mi++) {
                int ra = aRow0 + m0 + mi * 16 + g;
                if (ra < aN) {
                    float2 xv = *(float2*)(a.X + (size_t)ra * 128 + col);
                    float y0 = tms * xv.x + sk * (acc[mi][ni][0] + bb0);
                    float y1 = tms * xv.y + sk * (acc[mi][ni][1] + bb1);
                    *(float2*)(a.X + (size_t)ra * 128 + col) = make_float2(y0, y1);
                    psum[mi][0] += y0 + y1;
                    psq[mi][0]  += y0 * y0 + y1 * y1;
                }
                if (ra + 8 < aN) {
                    float2 xv = *(float2*)(a.X + (size_t)(ra + 8) * 128 + col);
                    float y2 = tms * xv.x + sk * (acc[mi][ni][2] + bb0);
                    float y3 = tms * xv.y + sk * (acc[mi][ni][3] + bb1);
                    *(float2*)(a.X + (size_t)(ra + 8) * 128 + col) = make_float2(y2, y3);
                    psum[mi][1] += y2 + y3;
                    psq[mi][1]  += y2 * y2 + y3 * y3;
                }
            }
        }
#pragma unroll
        for (int mi = 0; mi < 2; mi++)
#pragma unroll
            for (int hh = 0; hh < 2; hh++) {
                float s = psum[mi][hh], q = psq[mi][hh];
                s += __shfl_xor_sync(0xffffffffu, s, 1);
                s += __shfl_xor_sync(0xffffffffu, s, 2);
                q += __shfl_xor_sync(0xffffffffu, q, 1);
                q += __shfl_xor_sync(0xffffffffu, q, 2);
                if (c == 0) {
                    int rl = m0 + mi * 16 + g + hh * 8;
                    atomicAdd(&rs[rl], s);
                    atomicAdd(&rq[rl], q);
                }
            }
        __syncthreads();

#pragma unroll
        for (int ni = 0; ni < 8; ni++) {
            int col = n0 + ni * 8 + 2 * c;
            float g0 = lng[col], g1 = lng[col + 1];
            float h0 = lnb[col], h1 = lnb[col + 1];
#pragma unroll
            for (int mi = 0; mi < 2; mi++) {
#pragma unroll
                for (int hh = 0; hh < 2; hh++) {
                    int rl = m0 + mi * 16 + g + hh * 8;
                    int ra = aRow0 + rl;
                    if (ra < aN) {
                        float mean = rs[rl] * (1.f / 128.f);
                        float var  = rq[rl] * (1.f / 128.f) - mean * mean;
                        float rstd = rsqrtf(var + 1e-5f);
                        float2 yv = *(float2*)(a.X + (size_t)ra * 128 + col);
                        float o0 = (yv.x - mean) * rstd * g0 + h0;
                        float o1 = (yv.y - mean) * rstd * g1 + h1;
                        store_split(o0, o1, a.X, a.Xh, a.Xl, (size_t)ra * 128 + col);
                    }
                }
            }
        }
    }
}

// ---------------------------------------------------------------------------
// Fold relation transforms into projection weights (and priors into k)
// ---------------------------------------------------------------------------
__global__ void fold_weights(const float* __restrict__ Wk, const float* __restrict__ bk,
                             const float* __restrict__ Wv, const float* __restrict__ bv,
                             const float* __restrict__ a_rel, const float* __restrict__ m_rel,
                             const float* __restrict__ p_rel,
                             float* __restrict__ WkE, float* __restrict__ bkE,
                             float* __restrict__ WvE, float* __restrict__ bvE) {
    int idx = blockIdx.x * blockDim.x + threadIdx.x;
    if (idx >= 4 * 129 * 128) return;
    int combo = idx / (129 * 128);
    int rem   = idx % (129 * 128);
    int r  = rem >> 7;
    int he = rem & 127;
    int h = he >> 4, e = he & 15;
    const float* aa = a_rel + ((size_t)combo * 8 + h) * 256 + e;
    const float* mm = m_rel + ((size_t)combo * 8 + h) * 256 + e;
    float ps = p_rel[combo * 8 + h] * 0.25f;

    const float* kr = (r < 128) ? (Wk + (size_t)combo * 16384 + (size_t)r * 128 + h * 16)
                                : (bk + (size_t)combo * 128 + h * 16);
    const float* vr = (r < 128) ? (Wv + (size_t)combo * 16384 + (size_t)r * 128 + h * 16)
                                : (bv + (size_t)combo * 128 + h * 16);
    float sk = 0.f, sv = 0.f;
#pragma unroll
    for (int d = 0; d < 16; d++) {
        sk += kr[d] * aa[d * 16];
        sv += vr[d] * mm[d * 16];
    }
    sk *= ps;
    if (r < 128) {
        WkE[(size_t)combo * 16384 + (size_t)r * 128 + he] = sk;
        WvE[(size_t)combo * 16384 + (size_t)r * 128 + he] = sv;
    } else {
        bkE[combo * 128 + he] = sk;
        bvE[combo * 128 + he] = sv;
    }
}

// ---------------------------------------------------------------------------
// Pre-split input-projection weights (2 mats): fp32 [k][n] -> bf16 hi/lo [n][k]
// ---------------------------------------------------------------------------
__global__ void bsplit_in(const float* __restrict__ Wdev, const float* __restrict__ Wfeat,
                          __nv_bfloat16* HDI, __nv_bfloat16* LDI,
                          __nv_bfloat16* HFI, __nv_bfloat16* LFI) {
    int i = blockIdx.x * blockDim.x + threadIdx.x;
    if (i >= 2 * 16384) return;
    int mat = i >> 14, rem = i & 16383;
    int n = rem >> 7, k = rem & 127;
    const float* src = mat ? Wfeat : Wdev;
    __nv_bfloat16* hi = mat ? HFI : HDI;
    __nv_bfloat16* lo = mat ? LFI : LDI;
    float x = src[(size_t)k * 128 + n];
    __nv_bfloat16 h = __float2bfloat16(x);
    hi[(size_t)n * 128 + k] = h;
    lo[(size_t)n * 128 + k] = __float2bfloat16(x - __bfloat162float(h));
}

// ---------------------------------------------------------------------------
// Pre-split the 16 layer matrices: mats 0-3 Wq, 4-7 WkE, 8-11 WvE, 12-15 Wa
// ---------------------------------------------------------------------------
__global__ void bsplit_rest(const float* __restrict__ Wq,  const float* __restrict__ WkE,
                            const float* __restrict__ WvE, const float* __restrict__ Wa,
                            __nv_bfloat16* HQ,  __nv_bfloat16* LQ,
                            __nv_bfloat16* HK,  __nv_bfloat16* LK,
                            __nv_bfloat16* HV,  __nv_bfloat16* LV,
                            __nv_bfloat16* HA,  __nv_bfloat16* LA) {
    int i = blockIdx.x * blockDim.x + threadIdx.x;
    if (i >= 16 * 16384) return;
    int mat = i >> 14, rem = i & 16383;
    int n = rem >> 7, k = rem & 127;
    int f = mat >> 2, cc = mat & 3;
    size_t off = (size_t)cc * 16384;
    const float* src = (f == 0) ? Wq : (f == 1) ? WkE : (f == 2) ? WvE : Wa;
    __nv_bfloat16* hi = (f == 0) ? HQ : (f == 1) ? HK : (f == 2) ? HV : HA;
    __nv_bfloat16* lo = (f == 0) ? LQ : (f == 1) ? LK : (f == 2) ? LV : LA;
    float x = src[off + (size_t)k * 128 + n];
    __nv_bfloat16 h = __float2bfloat16(x);
    hi[off + (size_t)n * 128 + k] = h;
    lo[off + (size_t)n * 128 + k] = __float2bfloat16(x - __bfloat162float(h));
}

// ---------------------------------------------------------------------------
// CSR build (both edge types fused per kernel)
// ---------------------------------------------------------------------------
__global__ void hist2(const int* __restrict__ dstF, const int* __restrict__ dstD,
                      int* __restrict__ cnt) {
    int i = blockIdx.x * blockDim.x + threadIdx.x;
    if (i >= 2 * EE) return;
    if (i < EE) atomicAdd(&cnt[dstF[i]], 1);
    else        atomicAdd(&cnt[NF + dstD[i - EE]], 1);
}

__global__ void bsum2(const int* __restrict__ cnt, int* __restrict__ bsum) {
    __shared__ int sh[512];
    int b = blockIdx.x, t = threadIdx.x;
    const int* arr; int g, lim;
    if (b < NBF) { arr = cnt;      g = b * 512 + t;         lim = NF; }
    else         { arr = cnt + NF; g = (b - NBF) * 512 + t; lim = ND; }
    sh[t] = (g < lim) ? arr[g] : 0;
    __syncthreads();
#pragma unroll
    for (int off = 256; off; off >>= 1) {
        if (t < off) sh[t] += sh[t + off];
        __syncthreads();
    }
    if (t == 0) bsum[b] = sh[0];
}

__global__ void scan2(int* __restrict__ bsum) {
    __shared__ int sh[128];
    int t = threadIdx.x;
    int base = (blockIdx.x == 0) ? 0 : NBF;
    int nb   = (blockIdx.x == 0) ? NBF : NBD;
    int v = (t < nb) ? bsum[base + t] : 0;
    sh[t] = v;
    __syncthreads();
#pragma unroll
    for (int off = 1; off < 128; off <<= 1) {
        int u = (t >= off) ? sh[t - off] : 0;
        __syncthreads();
        sh[t] += u;
        __syncthreads();
    }
    if (t < nb) bsum[base + t] = sh[t] - v;
}

__global__ void rowptr2(const int* __restrict__ cnt, const int* __restrict__ bsum,
                        int* __restrict__ rpf, int* __restrict__ rpd,
                        int* __restrict__ cur) {
    __shared__ int sh[512];
    int b = blockIdx.x, t = threadIdx.x;
    const int* arr; int* rp; int g, lim, curOff;
    if (b < NBF) { arr = cnt;      rp = rpf; g = b * 512 + t;         lim = NF; curOff = 0; }
    else         { arr = cnt + NF; rp = rpd; g = (b - NBF) * 512 + t; lim = ND; curOff = NF; }
    int base = bsum[b];
    int v = (g < lim) ? arr[g] : 0;
    sh[t] = v;
    __syncthreads();
    for (int off = 1; off < 512; off <<= 1) {
        int u = (t >= off) ? sh[t - off] : 0;
        __syncthreads();
        sh[t] += u;
        __syncthreads();
    }
    if (g < lim) { rp[g] = base + sh[t] - v; cur[curOff + g] = 0; }
    if (t == 0 && b == 0)   rpf[NF] = EE;
    if (t == 0 && b == NBF) rpd[ND] = EE;
}

__global__ void fill2(const int* __restrict__ srcF, const int* __restrict__ dstF,
                      const int* __restrict__ srcD, const int* __restrict__ dstD,
                      const int* __restrict__ rpf, const int* __restrict__ rpd,
                      int* __restrict__ cur, int* __restrict__ cdf, int* __restrict__ cfd) {
    int i = blockIdx.x * blockDim.x + threadIdx.x;
    if (i >= 2 * EE) return;
    if (i < EE) {
        int d = dstF[i];
        int pos = rpf[d] + atomicAdd(&cur[d], 1);
        cdf[pos] = srcF[i];
    } else {
        int j = i - EE;
        int d = dstD[j];
        int pos = rpd[d] + atomicAdd(&cur[NF + d], 1);
        cfd[pos] = srcD[j];
    }
}

// ---------------------------------------------------------------------------
// Edge aggregation, both edge types in one launch. One warp per dst node.
// 2-wide edge ILP. Writes agg as bf16 hi/lo (pre-split for the MODE2 GEMM).
// ---------------------------------------------------------------------------
__global__ void edge_agg2(const int* __restrict__ rpf, const int* __restrict__ cdf,
                          const int* __restrict__ rpd, const int* __restrict__ cfd,
                          const float* __restrict__ q, const __half* __restrict__ ktv,
                          __nv_bfloat16* __restrict__ aggh, __nv_bfloat16* __restrict__ aggl) {
    int w = (blockIdx.x * blockDim.x + threadIdx.x) >> 5;
    if (w >= NT) return;
    int lane = threadIdx.x & 31;
    bool isF = w < NF;
    int wi = isF ? w : (w - NF);
    int dstRow = isF ? (ND + wi) : wi;
    const int* rp  = isF ? rpf : rpd;
    const int* col = isF ? cdf : cfd;
    int srcBase = isF ? 0 : ND;

    float4 q4 = *(const float4*)(q + (size_t)dstRow * 128 + lane * 4);
    float4 acc = make_float4(0.f, 0.f, 0.f, 0.f);
    float ssum = 0.f;
    int beg = rp[wi], end = rp[wi + 1];
    int n = end - beg;

    auto ldkv = [&](int i) {
        int s = col[beg + i];
        return __ldg((const uint4*)(ktv + (size_t)(srcBase + s) * 256 + lane * 8));
    };
    auto proc = [&](uint4 ld) {
        float2 k01 = __half22float2(*(__half2*)&ld.x);
        float2 k23 = __half22float2(*(__half2*)&ld.y);
        float p = q4.x * k01.x + q4.y * k01.y + q4.z * k23.x + q4.w * k23.y;
        p += __shfl_xor_sync(0xffffffffu, p, 1);
        p += __shfl_xor_sync(0xffffffffu, p, 2);
        float ex = __expf(fminf(p, 80.f));
        float2 v01 = __half22float2(*(__half2*)&ld.z);
        float2 v23 = __half22float2(*(__half2*)&ld.w);
        ssum += ex;
        acc.x += ex * v01.x; acc.y += ex * v01.y;
        acc.z += ex * v23.x; acc.w += ex * v23.y;
    };

    uint4 c0 = {}, c1 = {};
    if (n > 0) c0 = ldkv(0);
    if (n > 1) c1 = ldkv(1);
    for (int i = 0; i < n; i += 2) {
        uint4 p0 = {}, p1 = {};
        if (i + 2 < n) p0 = ldkv(i + 2);
        if (i + 3 < n) p1 = ldkv(i + 3);
        proc(c0);
        if (i + 1 < n) proc(c1);
        c0 = p0; c1 = p1;
    }

    float inv = __frcp_rn(ssum + 1e-16f);
    float g0 = gelu_exact(acc.x * inv);
    float g1 = gelu_exact(acc.y * inv);
    float g2 = gelu_exact(acc.z * inv);
    float g3 = gelu_exact(acc.w * inv);

    size_t base = (size_t)dstRow * 128 + lane * 4;
    unsigned h01, l01, h23, l23;
    split_pair(make_float2(g0, g1), h01, l01);
    split_pair(make_float2(g2, g3), h23, l23);
    *(unsigned*)(aggh + base)     = h01;
    *(unsigned*)(aggh + base + 2) = h23;
    *(unsigned*)(aggl + base)     = l01;
    *(unsigned*)(aggl + base + 2) = l23;
}

// ---------------------------------------------------------------------------
// Output head: out[ND,32] = X[0:ND,128] @ W[128,32] + b
// ---------------------------------------------------------------------------
__global__ void out_gemm(const float* __restrict__ x, const float* __restrict__ W,
                         const float* __restrict__ b, float* __restrict__ out) {
    size_t idx = (size_t)blockIdx.x * blockDim.x + threadIdx.x;
    if (idx >= (size_t)ND * OUTC) return;
    int n = (int)(idx >> 5), cc = (int)(idx & 31);
    const float* xr = x + (size_t)n * 128;
    float s = b[cc];
#pragma unroll 8
    for (int k = 0; k < 128; k++) s += xr[k] * W[k * OUTC + cc];
    out[idx] = s;
}

// ---------------------------------------------------------------------------
// Host orchestration. Fork/join: s2 = CSR build, s3 = weight prep.
// Streams/events are created ONCE, on the first (eager, uncaptured) call —
// the harness runs a correctness call before capture, so no resource creation
// happens during capture. Non-blocking streams avoid legacy-stream
// serialization so the forked branches genuinely overlap in the graph.
// ---------------------------------------------------------------------------
static inline int cdiv(long long a, long long b) { return (int)((a + b - 1) / b); }

extern "C" void kernel_launch(void* const* d_in, const int* in_sizes, int n_in,
                              void* d_out, int out_size) {
    (void)in_sizes; (void)n_in; (void)out_size;

    const float* x_device = (const float*)d_in[0];
    const float* x_feature = (const float*)d_in[1];
    const int* e_df_src = (const int*)d_in[2];
    const int* e_df_dst = (const int*)d_in[3];
    const int* e_fd_src = (const int*)d_in[4];
    const int* e_fd_dst = (const int*)d_in[5];
    const float* W_dev_in = (const float*)d_in[6];
    const float* b_dev_in = (const float*)d_in[7];
    const float* W_feat_in = (const float*)d_in[8];
    const float* b_feat_in = (const float*)d_in[9];
    const float* Wk = (const float*)d_in[10];
    const float* bk = (const float*)d_in[11];
    const float* Wq = (const float*)d_in[12];
    const float* bq = (const float*)d_in[13];
    const float* Wv = (const float*)d_in[14];
    const float* bv = (const float*)d_in[15];
    const float* a_rel = (const float*)d_in[16];
    const float* m_rel = (const float*)d_in[17];
    const float* p_rel = (const float*)d_in[18];
    const float* Wa = (const float*)d_in[19];
    const float* ba = (const float*)d_in[20];
    const float* skip = (const float*)d_in[21];
    const float* ln_g = (const float*)d_in[22];
    const float* ln_b = (const float*)d_in[23];
    const float* W_out = (const float*)d_in[24];
    const float* b_out = (const float*)d_in[25];
    float* out = (float*)d_out;

    float* pool = nullptr;
    cudaGetSymbolAddress((void**)&pool, g_pool);

    float* X   = pool + OFF_X;
    float* Q   = pool + OFF_Q;
    __half* KTV = (__half*)(pool + OFF_KTV);
    __nv_bfloat16* Xh  = (__nv_bfloat16*)(pool + OFF_XH);
    __nv_bfloat16* Xl  = (__nv_bfloat16*)(pool + OFF_XL);
    __nv_bfloat16* AGH = (__nv_bfloat16*)(pool + OFF_AGH);
    __nv_bfloat16* AGL = (__nv_bfloat16*)(pool + OFF_AGL);
    float* WkE = pool + OFF_WKE;  float* WvE = pool + OFF_WVE;
    float* bkE = pool + OFF_BKE;  float* bvE = pool + OFF_BVE;
    __nv_bfloat16* HQ = (__nv_bfloat16*)(pool + OFF_HQ);
    __nv_bfloat16* LQ = (__nv_bfloat16*)(pool + OFF_LQ);
    __nv_bfloat16* HK = (__nv_bfloat16*)(pool + OFF_HK);
    __nv_bfloat16* LK = (__nv_bfloat16*)(pool + OFF_LK);
    __nv_bfloat16* HV = (__nv_bfloat16*)(pool + OFF_HV);
    __nv_bfloat16* LV = (__nv_bfloat16*)(pool + OFF_LV);
    __nv_bfloat16* HA = (__nv_bfloat16*)(pool + OFF_HA);
    __nv_bfloat16* LA = (__nv_bfloat16*)(pool + OFF_LA);
    __nv_bfloat16* HDI = (__nv_bfloat16*)(pool + OFF_HDI);
    __nv_bfloat16* LDI = (__nv_bfloat16*)(pool + OFF_LDI);
    __nv_bfloat16* HFI = (__nv_bfloat16*)(pool + OFF_HFI);
    __nv_bfloat16* LFI = (__nv_bfloat16*)(pool + OFF_LFI);
    int* rpf = (int*)(pool + OFF_RPF);
    int* rpd = (int*)(pool + OFF_RPD);
    int* cdf = (int*)(pool + OFF_CDF);
    int* cfd = (int*)(pool + OFF_CFD);
    int* cnt = (int*)(pool + OFF_CNT);
    int* cur = (int*)(pool + OFF_CUR);
    int* bsum = (int*)(pool + OFF_BSUM);

    const int gBlkD = cdiv(ND, 128), gBlkF = cdiv(NF, 128);
    const int gBlk = gBlkD + gBlkF;

    // One-time resource creation (first call is eager per harness contract)
    static cudaStream_t s2 = nullptr, s3 = nullptr;
    static cudaEvent_t evRoot = nullptr, evCsr = nullptr, evW = nullptr;
    if (s2 == nullptr) {
        cudaStreamCreateWithFlags(&s2, cudaStreamNonBlocking);
        cudaStreamCreateWithFlags(&s3, cudaStreamNonBlocking);
        cudaEventCreateWithFlags(&evRoot, cudaEventDisableTiming);
        cudaEventCreateWithFlags(&evCsr, cudaEventDisableTiming);
        cudaEventCreateWithFlags(&evW, cudaEventDisableTiming);
    }

    cudaEventRecord(evRoot, 0);
    cudaStreamWaitEvent(s2, evRoot, 0);
    cudaStreamWaitEvent(s3, evRoot, 0);

    // ---- branch s2: CSR build (both edge types) ----
    cudaMemsetAsync(cnt, 0, NT * sizeof(int), s2);
    hist2<<<cdiv(2 * EE, 256), 256, 0, s2>>>(e_df_dst, e_fd_dst, cnt);
    bsum2<<<NBF + NBD, 512, 0, s2>>>(cnt, bsum);
    scan2<<<2, 128, 0, s2>>>(bsum);
    rowptr2<<<NBF + NBD, 512, 0, s2>>>(cnt, bsum, rpf, rpd, cur);
    fill2<<<cdiv(2 * EE, 256), 256, 0, s2>>>(e_df_src, e_df_dst, e_fd_src, e_fd_dst,
                                             rpf, rpd, cur, cdf, cfd);
    cudaEventRecord(evCsr, s2);

    // ---- branch s3: fold relation transforms + split the 16 layer matrices ----
    fold_weights<<<cdiv(4 * 129 * 128, 256), 256, 0, s3>>>(Wk, bk, Wv, bv,
                                                           a_rel, m_rel, p_rel,
                                                           WkE, bkE, WvE, bvE);
    bsplit_rest<<<cdiv(16 * 16384, 256), 256, 0, s3>>>(Wq, WkE, WvE, Wa,
                                                       HQ, LQ, HK, LK, HV, LV, HA, LA);
    cudaEventRecord(evW, s3);

    // ---- main: input-weight split + input projections + ReLU (merged D/F) ----
    bsplit_in<<<cdiv(2 * 16384, 256), 256>>>(W_dev_in, W_feat_in, HDI, LDI, HFI, LFI);
    {
        GArgs a = {};
        a.AfD = x_device; a.AfF = x_feature;
        a.H0 = HDI; a.L0 = LDI; a.H1 = HFI; a.L1 = LFI;
        a.b0 = b_dev_in; a.b1 = b_feat_in;
        a.X = X; a.Xh = Xh; a.Xl = Xl;
        a.layer = 0; a.blkD = gBlkD;
        gemm_tc<1, 0><<<gBlk, 256>>>(a);
    }

    cudaStreamWaitEvent(0, evW, 0);   // layer weights ready before qkv

    for (int l = 0; l < NLYR; l++) {
        // fused q / kt / vt projections (merged D/F, gridDim.y = 3, 2-term split)
        {
            GArgs a = {};
            a.Ah = Xh; a.Al = Xl;
            a.H0 = HQ; a.L0 = LQ; a.H1 = HK; a.L1 = LK; a.H2 = HV; a.L2 = LV;
            a.b0 = bq; a.b1 = bkE; a.b2 = bvE;
            a.Q = Q; a.KTV = KTV;
            a.layer = l; a.blkD = gBlkD;
            gemm_tc<0, 1><<<dim3(gBlk, 3), 256>>>(a);
        }
        if (l == 0) cudaStreamWaitEvent(0, evCsr, 0);  // CSR ready before first edge pass
        // edge aggregation (both edge types)
        edge_agg2<<<cdiv((long long)NT * 32, 256), 256>>>(rpf, cdf, rpd, cfd,
                                                          Q, KTV, AGH, AGL);
        // Wa GEMM + fused skip + residual + LayerNorm (merged D/F)
        {
            GArgs a = {};
            a.Ah = AGH; a.Al = AGL;
            a.H0 = HA; a.L0 = LA;
            a.b0 = ba;
            a.X = X; a.Xh = Xh; a.Xl = Xl;
            a.skipv = skip; a.lng = ln_g; a.lnb = ln_b;
            a.layer = l; a.blkD = gBlkD;
            gemm_tc<2, 1><<<gBlk, 256>>>(a);
        }
    }

    out_gemm<<<cdiv((long long)ND * OUTC, 256), 256>>>(X, W_out, b_out, out);
}